// round 11
// baseline (speedup 1.0000x reference)
#include <cuda_runtime.h>

#define IN_    26
#define H1_    64
#define H2_    32
#define T_     1000
#define ROWS_  4
#define NCB_   128
#define NPROD_ 20
#define CHUNK_ 5
#define NCHUNK_ (T_ / CHUNK_)
#define THREADS_ 384

#define L2E_      1.4426950408889634f
#define TWO_L2E_  2.8853900817779268f

typedef unsigned long long u64;

// xg[t][cb][grow][r] as float4 over r; +1 step pad for prefetch overrun
__device__ float4 xg_buf[(T_ + 1) * NCB_ * 256];
__device__ int prog_g[NCB_];   // BSS zero at module load; persists across replays (by design)

__device__ __forceinline__ void fma2(u64 &d, u64 a, u64 b) {
    asm("fma.rn.f32x2 %0, %1, %2, %0;" : "+l"(d) : "l"(a), "l"(b));
}
__device__ __forceinline__ float lo32(u64 v){ return __uint_as_float((unsigned)v); }
__device__ __forceinline__ float hi32(u64 v){ return __uint_as_float((unsigned)(v >> 32)); }
__device__ __forceinline__ u64 packf(float lo, float hi){
    return ((u64)__float_as_uint(hi) << 32) | (u64)__float_as_uint(lo);
}
__device__ __forceinline__ float ex2a(float x){ float r; asm("ex2.approx.f32 %0, %1;" : "=f"(r) : "f"(x)); return r; }
__device__ __forceinline__ float rcpa(float x){ float r; asm("rcp.approx.f32 %0, %1;" : "=f"(r) : "f"(x)); return r; }
__device__ __forceinline__ float tanh_true(float c) {
    float u = ex2a(fminf(TWO_L2E_ * c, 50.0f));
    return (u - 1.0f) * rcpa(u + 1.0f);
}

// shared memory (both roles; ~6 KB total)
__shared__ float h1s[2 * ROWS_ * 68];
__shared__ float h2s[2 * ROWS_ * 36];
__shared__ float sfc[64];
__shared__ __align__(16) float xstage[ROWS_][CHUNK_][28];

__global__ void __launch_bounds__(THREADS_, 1) audiolstm_fused_kernel(
    const float* __restrict__ x,
    const float* __restrict__ w_ih1, const float* __restrict__ w_hh1,
    const float* __restrict__ b_ih1, const float* __restrict__ b_hh1,
    const float* __restrict__ w_ih2, const float* __restrict__ w_hh2,
    const float* __restrict__ b_ih2, const float* __restrict__ b_hh2,
    const float* __restrict__ w_fc1, const float* __restrict__ b_fc1,
    const float* __restrict__ w_fc2, const float* __restrict__ b_fc2,
    float* __restrict__ out)
{
    const int tid = threadIdx.x;
    const int bid = blockIdx.x;

    if (bid < NPROD_) {
        // ===================== PRODUCER: xg = (x * W_ih1^T) * log2e =====================
        const int cb0 = bid * NCB_ / NPROD_;
        const int cb1 = (bid + 1) * NCB_ / NPROD_;
        const int ncb = cb1 - cb0;
        const int nit = NCHUNK_ * ncb;        // chunk-major over owned cbs

        // compute threads: tid<320; tt = tid>>6 (0..4); gate-rows rb+{0,64,128,192}
        const int rb  = tid & 63;
        const int ttq = tid >> 6;
        u64 w13[4][14];
        if (tid < 320) {
#pragma unroll
            for (int b = 0; b < 4; ++b) {
                const float* wi = w_ih1 + (rb + 64 * b) * IN_;
#pragma unroll
                for (int j = 0; j < 13; ++j) w13[b][j] = packf(wi[2*j] * L2E_, wi[2*j+1] * L2E_);
                w13[b][13] = 0ull;
            }
        }

        // prefetch-rotated staging: 520 x-floats per (cb,chunk)
        float pf0 = 0.0f, pf1 = 0.0f;
        {
            const int cb = cb0, chunk = 0;
            int i0 = tid, i1 = tid + THREADS_;
            if (i0 < 520) { int r = i0/130, rem = i0-130*r, i = rem/5, tt = rem-5*i;
                pf0 = x[((cb*ROWS_+r)*IN_+i)*T_ + chunk*CHUNK_ + tt]; }
            if (i1 < 520) { int r = i1/130, rem = i1-130*r, i = rem/5, tt = rem-5*i;
                pf1 = x[((cb*ROWS_+r)*IN_+i)*T_ + chunk*CHUNK_ + tt]; }
        }

        for (int it = 0; it < nit; ++it) {
            const int chunk = it / ncb;
            const int cb    = cb0 + (it - chunk * ncb);
            // store staged values
            {
                int i0 = tid, i1 = tid + THREADS_;
                if (i0 < 520) { int r = i0/130, rem = i0-130*r, i = rem/5, tt = rem-5*i;
                    xstage[r][tt][i] = pf0; }
                if (i1 < 520) { int r = i1/130, rem = i1-130*r, i = rem/5, tt = rem-5*i;
                    xstage[r][tt][i] = pf1; }
                if (tid < 40) { int r = tid/10, q = tid-10*r;
                    xstage[r][q>>1][26 + (q&1)] = 0.0f; }
            }
            __syncthreads();
            // prefetch next iteration's x
            if (it + 1 < nit) {
                const int ch2 = (it+1) / ncb;
                const int cb2 = cb0 + ((it+1) - ch2 * ncb);
                int i0 = tid, i1 = tid + THREADS_;
                if (i0 < 520) { int r = i0/130, rem = i0-130*r, i = rem/5, tt = rem-5*i;
                    pf0 = x[((cb2*ROWS_+r)*IN_+i)*T_ + ch2*CHUNK_ + tt]; }
                if (i1 < 520) { int r = i1/130, rem = i1-130*r, i = rem/5, tt = rem-5*i;
                    pf1 = x[((cb2*ROWS_+r)*IN_+i)*T_ + ch2*CHUNK_ + tt]; }
            }
            // compute xg for (cb, chunk), my tt slice
            if (tid < 320) {
                const int step = chunk * CHUNK_ + ttq;
#pragma unroll
                for (int b = 0; b < 4; ++b) {
                    float4 v;
                    float* vp = &v.x;
#pragma unroll
                    for (int r = 0; r < 4; ++r) {
                        u64 acc = 0ull;
                        const ulonglong2* xp = (const ulonglong2*)&xstage[r][ttq][0];
#pragma unroll
                        for (int p = 0; p < 7; ++p) {
                            ulonglong2 q = xp[p];
                            fma2(acc, w13[b][2*p],   q.x);
                            fma2(acc, w13[b][2*p+1], q.y);
                        }
                        vp[r] = lo32(acc) + hi32(acc);
                    }
                    xg_buf[((size_t)step * NCB_ + cb) * 256 + rb + 64 * b] = v;
                }
            }
            __threadfence();
            __syncthreads();
            if (tid == 0) atomicExch(&prog_g[cb], (chunk + 1) * CHUNK_);
        }
        return;
    }

    // ===================== CONSUMER: recurrent kernel (R9 body + pacing) =====================
    const int cb   = bid - NPROD_;
    const int row0 = cb * ROWS_;
    const int lane4 = tid & 3;
    const bool p1 = (tid < 256);
    const bool isg = (lane4 == 2);

    u64 wu[48];
    float biasv;
    int grow1 = 0;
    if (p1) {
        const int G = tid >> 2;
        grow1 = lane4 * 64 + G;
        const float* wh = w_hh1 + grow1 * H1_;
#pragma unroll
        for (int p = 0; p < 32; ++p) wu[p] = packf(wh[2*p] * L2E_, wh[2*p+1] * L2E_);
#pragma unroll
        for (int p = 32; p < 48; ++p) wu[p] = 0ull;
        biasv = (b_ih1[grow1] + b_hh1[grow1]) * L2E_;
    } else {
        const int J = (tid - 256) >> 2;
        const int row = lane4 * 32 + J;
        const float* wi = w_ih2 + row * H1_;
        const float* wh = w_hh2 + row * H2_;
#pragma unroll
        for (int p = 0; p < 32; ++p) wu[p] = packf(wi[2*p] * L2E_, wi[2*p+1] * L2E_);
#pragma unroll
        for (int p = 0; p < 16; ++p) wu[32+p] = packf(wh[2*p] * L2E_, wh[2*p+1] * L2E_);
        biasv = (b_ih2[row] + b_hh2[row]) * L2E_;
    }
    const u64 bias_u = (u64)__float_as_uint(biasv);
    const int unitG = p1 ? (tid >> 2) : ((tid - 256) >> 2);

    for (int i = tid; i < 2 * ROWS_ * 68; i += THREADS_) h1s[i] = 0.0f;
    for (int i = tid; i < 2 * ROWS_ * 36; i += THREADS_) h2s[i] = 0.0f;

    // wait for first xg chunks (real wait on first launch; fast-path on replays)
    if (tid == 0) {
        while (atomicAdd(&prog_g[cb], 0) < 30) { }
        __threadfence();
    }
    __syncthreads();

    float cst = 0.0f;
    float4 xgv = make_float4(0,0,0,0);
    const float4* xgp = xg_buf + (size_t)cb * 256 + grow1;
    if (p1) xgv = xgp[0];

    for (int s = 0; s < T_; ++s) {
        if (s && (s % 25) == 0) {
            if (tid == 0) {
                int need = s + 30; if (need > T_) need = T_;
                while (atomicAdd(&prog_g[cb], 0) < need) { }
                __threadfence();
            }
            __syncthreads();
        }
        const int pb = s & 1;
        if (p1) {
            float4 xgn = xgp[(size_t)(s + 1) * NCB_ * 256];
            const float* xga = &xgv.x;
            float a[4];
#pragma unroll
            for (int r = 0; r < 4; ++r) {
                u64 accA = bias_u;
                u64 accB = 0ull;
                const ulonglong2* hp = (const ulonglong2*)(h1s + (pb * ROWS_ + r) * 68);
#pragma unroll
                for (int p = 0; p < 8; ++p) {
                    ulonglong2 v = hp[p];
                    fma2(accA, wu[2*p],   v.x);
                    fma2(accA, wu[2*p+1], v.y);
                }
#pragma unroll
                for (int p = 8; p < 16; ++p) {
                    ulonglong2 v = hp[p];
                    fma2(accB, wu[2*p],   v.x);
                    fma2(accB, wu[2*p+1], v.y);
                }
                float t = (lo32(accA) + hi32(accA)) + (lo32(accB) + hi32(accB)) + xga[r];
                float u = ex2a(fminf(isg ? 2.0f * t : -t, 50.0f));
                a[r] = isg ? (u - 1.0f) * rcpa(u + 1.0f) : rcpa(1.0f + u);
            }
            {
                float e0 = __shfl_xor_sync(0xffffffffu, (lane4 & 2) ? a[0] : a[2], 2, 4);
                float e1 = __shfl_xor_sync(0xffffffffu, (lane4 & 2) ? a[1] : a[3], 2, 4);
                if (lane4 & 2) { a[0] = e0; a[1] = e1; } else { a[2] = e0; a[3] = e1; }
                float f0 = __shfl_xor_sync(0xffffffffu, (lane4 & 1) ? a[0] : a[1], 1, 4);
                float f1 = __shfl_xor_sync(0xffffffffu, (lane4 & 1) ? a[2] : a[3], 1, 4);
                if (lane4 & 1) { a[0] = f0; a[2] = f1; } else { a[1] = f0; a[3] = f1; }
            }
            cst = fmaf(a[1], cst, a[0] * a[2]);
            float hv = a[3] * tanh_true(cst);
            h1s[((pb ^ 1) * ROWS_ + lane4) * 68 + unitG] = hv;
            xgv = xgn;
        }
        __syncthreads();
        if (!p1) {
            float a[4];
#pragma unroll
            for (int r = 0; r < 4; ++r) {
                u64 accA = bias_u;
                u64 accB = 0ull;
                const ulonglong2* hp1 = (const ulonglong2*)(h1s + ((pb ^ 1) * ROWS_ + r) * 68);
#pragma unroll
                for (int p = 0; p < 8; ++p) {
                    ulonglong2 v = hp1[p];
                    fma2(accA, wu[2*p],   v.x);
                    fma2(accA, wu[2*p+1], v.y);
                }
#pragma unroll
                for (int p = 8; p < 16; ++p) {
                    ulonglong2 v = hp1[p];
                    fma2(accB, wu[2*p],   v.x);
                    fma2(accB, wu[2*p+1], v.y);
                }
                const ulonglong2* hp2 = (const ulonglong2*)(h2s + (pb * ROWS_ + r) * 36);
#pragma unroll
                for (int p = 0; p < 8; ++p) {
                    ulonglong2 v = hp2[p];
                    fma2(accB, wu[32 + 2*p], v.x);
                    fma2(accB, wu[33 + 2*p], v.y);
                }
                float t = (lo32(accA) + hi32(accA)) + (lo32(accB) + hi32(accB));
                float u = ex2a(fminf(isg ? 2.0f * t : -t, 50.0f));
                a[r] = isg ? (u - 1.0f) * rcpa(u + 1.0f) : rcpa(1.0f + u);
            }
            {
                float e0 = __shfl_xor_sync(0xffffffffu, (lane4 & 2) ? a[0] : a[2], 2, 4);
                float e1 = __shfl_xor_sync(0xffffffffu, (lane4 & 2) ? a[1] : a[3], 2, 4);
                if (lane4 & 2) { a[0] = e0; a[1] = e1; } else { a[2] = e0; a[3] = e1; }
                float f0 = __shfl_xor_sync(0xffffffffu, (lane4 & 1) ? a[0] : a[1], 1, 4);
                float f1 = __shfl_xor_sync(0xffffffffu, (lane4 & 1) ? a[2] : a[3], 1, 4);
                if (lane4 & 1) { a[0] = f0; a[2] = f1; } else { a[1] = f0; a[3] = f1; }
            }
            cst = fmaf(a[1], cst, a[0] * a[2]);
            float hv = a[3] * tanh_true(cst);
            h2s[((pb ^ 1) * ROWS_ + lane4) * 36 + unitG] = hv;
        }
    }

    __syncthreads();
    // phase2(999): pb=1, wrote h2s buf 0
    if (tid < 64) {
        int r = tid & 3, f = tid >> 2;
        const float* hrow = h2s + (0 * ROWS_ + r) * 36;
        float acc = b_fc1[f];
#pragma unroll
        for (int k = 0; k < H2_; ++k) acc = fmaf(hrow[k], w_fc1[f * H2_ + k], acc);
        sfc[r * 16 + f] = fmaxf(acc, 0.0f);
    }
    __syncthreads();
    if (tid < 40) {
        int r = tid & 3, o = tid >> 2;
        float acc = b_fc2[o];
#pragma unroll
        for (int k = 0; k < 16; ++k) acc = fmaf(sfc[r * 16 + k], w_fc2[o * 16 + k], acc);
        out[(row0 + r) * 10 + o] = acc;
    }
}

extern "C" void kernel_launch(void* const* d_in, const int* in_sizes, int n_in,
                              void* d_out, int out_size) {
    const float* x     = (const float*)d_in[0];
    const float* w_ih1 = (const float*)d_in[1];
    const float* w_hh1 = (const float*)d_in[2];
    const float* b_ih1 = (const float*)d_in[3];
    const float* b_hh1 = (const float*)d_in[4];
    const float* w_ih2 = (const float*)d_in[5];
    const float* w_hh2 = (const float*)d_in[6];
    const float* b_ih2 = (const float*)d_in[7];
    const float* b_hh2 = (const float*)d_in[8];
    const float* w_fc1 = (const float*)d_in[9];
    const float* b_fc1 = (const float*)d_in[10];
    const float* w_fc2 = (const float*)d_in[11];
    const float* b_fc2 = (const float*)d_in[12];
    float* out = (float*)d_out;

    audiolstm_fused_kernel<<<NPROD_ + NCB_, THREADS_>>>(
        x, w_ih1, w_hh1, b_ih1, b_hh1,
        w_ih2, w_hh2, b_ih2, b_hh2,
        w_fc1, b_fc1, w_fc2, b_fc2, out);
}

// round 12
// speedup vs baseline: 1.7355x; 1.7355x over previous
#include <cuda_runtime.h>
#include <cuda_fp16.h>

#define IN_    26
#define H1_    64
#define H2_    32
#define T_     1000
#define ROWS_  4
#define NCB_   128
#define THREADS_ 512
#define PTT_   100

#define L2E_      1.4426950408889634f
#define TWO_L2E_  2.8853900817779268f

typedef unsigned long long u64;

// xg in fp16: [t][cb][grow][4 rows] as uint2 (4 halfs); +1 step pad for prefetch overrun
__device__ uint2 xg_h[(T_ + 1) * NCB_ * 256];

__device__ __forceinline__ void fma2(u64 &d, u64 a, u64 b) {
    asm("fma.rn.f32x2 %0, %1, %2, %0;" : "+l"(d) : "l"(a), "l"(b));
}
__device__ __forceinline__ float lo32(u64 v){ return __uint_as_float((unsigned)v); }
__device__ __forceinline__ float hi32(u64 v){ return __uint_as_float((unsigned)(v >> 32)); }
__device__ __forceinline__ u64 packf(float lo, float hi){
    return ((u64)__float_as_uint(hi) << 32) | (u64)__float_as_uint(lo);
}
__device__ __forceinline__ float ex2a(float x){ float r; asm("ex2.approx.f32 %0, %1;" : "=f"(r) : "f"(x)); return r; }
__device__ __forceinline__ float rcpa(float x){ float r; asm("rcp.approx.f32 %0, %1;" : "=f"(r) : "f"(x)); return r; }
__device__ __forceinline__ float tanh_true(float c) {
    float u = ex2a(fminf(TWO_L2E_ * c, 50.0f));
    return (u - 1.0f) * rcpa(u + 1.0f);
}
__device__ __forceinline__ float gate_act(float t, bool isg) {
    float u = ex2a(isg ? fminf(2.0f * t, 50.0f) : -t);
    return isg ? (u - 1.0f) * rcpa(u + 1.0f) : rcpa(1.0f + u);
}

// ===================== kernel 1: xg = (x * W_ih1^T) * log2e, fp16 out =====================
__global__ void __launch_bounds__(256) xg16_kernel(
    const float* __restrict__ x, const float* __restrict__ w_ih1)
{
    __shared__ __align__(16) float xt[ROWS_][PTT_][28];
    const int cb  = blockIdx.x;
    const int t0  = blockIdx.y * PTT_;
    const int tid = threadIdx.x;          // = gate row 0..255

    for (int idx = tid; idx < ROWS_ * IN_ * PTT_; idx += 256) {
        int r = idx / (IN_ * PTT_);
        int rem = idx - r * (IN_ * PTT_);
        int i = rem / PTT_, t = rem - i * PTT_;
        xt[r][t][i] = x[((cb * ROWS_ + r) * IN_ + i) * T_ + t0 + t];
    }
    for (int idx = tid; idx < ROWS_ * PTT_; idx += 256) {
        int r = idx / PTT_, t = idx - r * PTT_;
        xt[r][t][26] = 0.0f; xt[r][t][27] = 0.0f;
    }
    __syncthreads();

    u64 w[14];
    const float* wi = w_ih1 + tid * IN_;
#pragma unroll
    for (int j = 0; j < 13; ++j) w[j] = packf(wi[2*j] * L2E_, wi[2*j+1] * L2E_);
    w[13] = 0ull;

    uint2* dst = xg_h + (size_t)t0 * NCB_ * 256 + cb * 256 + tid;
    for (int t = 0; t < PTT_; ++t) {
        float v[4];
#pragma unroll
        for (int r = 0; r < ROWS_; ++r) {
            u64 acc = 0ull;
            const ulonglong2* xp = (const ulonglong2*)&xt[r][t][0];
#pragma unroll
            for (int p = 0; p < 7; ++p) {
                ulonglong2 q = xp[p];
                fma2(acc, w[2*p],   q.x);
                fma2(acc, w[2*p+1], q.y);
            }
            v[r] = lo32(acc) + hi32(acc);
        }
        __half2 h01 = __floats2half2_rn(v[0], v[1]);
        __half2 h23 = __floats2half2_rn(v[2], v[3]);
        uint2 st;
        st.x = *(unsigned*)&h01;
        st.y = *(unsigned*)&h23;
        dst[(size_t)t * NCB_ * 256] = st;
    }
}

// ===================== kernel 2: recurrent consumer =====================
// cc[buf][row][104]: cols 0..63 = h1, 64..95 = h2, pad
__shared__ __align__(16) float cc[2 * ROWS_ * 104];
__shared__ float sfc[64];

__global__ void __launch_bounds__(THREADS_, 1) audiolstm_kernel(
    const float* __restrict__ w_hh1,
    const float* __restrict__ b_ih1, const float* __restrict__ b_hh1,
    const float* __restrict__ w_ih2, const float* __restrict__ w_hh2,
    const float* __restrict__ b_ih2, const float* __restrict__ b_hh2,
    const float* __restrict__ w_fc1, const float* __restrict__ b_fc1,
    const float* __restrict__ w_fc2, const float* __restrict__ b_fc2,
    float* __restrict__ out)
{
    const int tid  = threadIdx.x;
    const int cb   = blockIdx.x;
    const int row0 = cb * ROWS_;
    const bool p1  = (tid < 256);

    for (int i = tid; i < 2 * ROWS_ * 104; i += THREADS_) cc[i] = 0.0f;

    float cst = 0.0f;

    if (p1) {
        // ============ phase1: LSTM1, 8 warps, full weights ============
        const int lane4 = tid & 3;
        const int G     = tid >> 2;
        const bool isg  = (lane4 == 2);
        const int grow  = lane4 * 64 + G;
        u64 wh[32];
        {
            const float* whp = w_hh1 + grow * H1_;
#pragma unroll
            for (int p = 0; p < 32; ++p) wh[p] = packf(whp[2*p] * L2E_, whp[2*p+1] * L2E_);
        }
        const u64 bias_u = (u64)__float_as_uint((b_ih1[grow] + b_hh1[grow]) * L2E_);
        __syncthreads();

        const uint2* xgp = xg_h + (size_t)cb * 256 + grow;
        uint2 xgv = xgp[0];

        for (int s = 0; s < T_; ++s) {
            const int pb = s & 1;
            uint2 xgn = xgp[(size_t)(s + 1) * NCB_ * 256];
            float2 f01 = __half22float2(*(__half2*)&xgv.x);
            float2 f23 = __half22float2(*(__half2*)&xgv.y);
            float xga[4] = {f01.x, f01.y, f23.x, f23.y};

            float a[4];
#pragma unroll
            for (int r = 0; r < 4; ++r) {
                u64 accA = bias_u, accB = 0ull;
                const ulonglong2* hp = (const ulonglong2*)(cc + (pb * ROWS_ + r) * 104);
#pragma unroll
                for (int p = 0; p < 8; ++p) {
                    ulonglong2 v = hp[p];
                    fma2(accA, wh[2*p],   v.x);
                    fma2(accA, wh[2*p+1], v.y);
                }
#pragma unroll
                for (int p = 8; p < 16; ++p) {
                    ulonglong2 v = hp[p];
                    fma2(accB, wh[2*p],   v.x);
                    fma2(accB, wh[2*p+1], v.y);
                }
                float t = (lo32(accA) + hi32(accA)) + (lo32(accB) + hi32(accB)) + xga[r];
                a[r] = gate_act(t, isg);
            }
            { // 4x4 quad transpose
                float e0 = __shfl_xor_sync(0xffffffffu, (lane4 & 2) ? a[0] : a[2], 2, 4);
                float e1 = __shfl_xor_sync(0xffffffffu, (lane4 & 2) ? a[1] : a[3], 2, 4);
                if (lane4 & 2) { a[0] = e0; a[1] = e1; } else { a[2] = e0; a[3] = e1; }
                float f0 = __shfl_xor_sync(0xffffffffu, (lane4 & 1) ? a[0] : a[1], 1, 4);
                float f1 = __shfl_xor_sync(0xffffffffu, (lane4 & 1) ? a[2] : a[3], 1, 4);
                if (lane4 & 1) { a[0] = f0; a[2] = f1; } else { a[1] = f0; a[3] = f1; }
            }
            cst = fmaf(a[1], cst, a[0] * a[2]);
            float hv = a[3] * tanh_true(cst);
            cc[((pb ^ 1) * ROWS_ + lane4) * 104 + G] = hv;
            xgv = xgn;
            __syncthreads();
        }
    } else {
        // ============ phase2: LSTM2, 8 warps, K-split halves ============
        const int idx   = tid - 256;
        const int lane  = idx & 31;
        const int half  = lane >> 4;
        const int lane4 = lane & 3;
        const int uin   = (lane >> 2) & 3;
        const int J     = (idx >> 5) * 4 + uin;   // unit 0..31
        const bool isg  = (lane4 == 2);
        const int grow  = lane4 * 32 + J;
        u64 wc[24];
        {
            const float* wi = w_ih2 + grow * H1_;
            const float* whp = w_hh2 + grow * H2_;
            const int base = half * 48;
#pragma unroll
            for (int j = 0; j < 24; ++j) {
                int f0 = base + 2*j, f1 = f0 + 1;
                float lo = (f0 < 64) ? wi[f0] : whp[f0 - 64];
                float hi = (f1 < 64) ? wi[f1] : whp[f1 - 64];
                wc[j] = packf(lo * L2E_, hi * L2E_);
            }
        }
        const u64 bias_u = (half == 0)
            ? (u64)__float_as_uint((b_ih2[grow] + b_hh2[grow]) * L2E_) : 0ull;
        __syncthreads();

        for (int s = 0; s < T_; ++s) {
            const int pb = s & 1;
            __syncthreads();    // pairs with phase1's end-of-step barrier: h1(s) ready
            float a[4];
#pragma unroll
            for (int r = 0; r < 4; ++r) {
                u64 accA = bias_u, accB = 0ull;
                const ulonglong2* P = (const ulonglong2*)(cc + ((pb ^ 1) * ROWS_ + r) * 104 + half * 48);
#pragma unroll
                for (int p = 0; p < 6; ++p) {
                    ulonglong2 v = P[p];
                    fma2(accA, wc[2*p],   v.x);
                    fma2(accA, wc[2*p+1], v.y);
                }
#pragma unroll
                for (int p = 6; p < 12; ++p) {
                    ulonglong2 v = P[p];
                    fma2(accB, wc[2*p],   v.x);
                    fma2(accB, wc[2*p+1], v.y);
                }
                float t = (lo32(accA) + hi32(accA)) + (lo32(accB) + hi32(accB));
                t += __shfl_xor_sync(0xffffffffu, t, 16, 32);
                a[r] = gate_act(t, isg);
            }
            {
                float e0 = __shfl_xor_sync(0xffffffffu, (lane4 & 2) ? a[0] : a[2], 2, 4);
                float e1 = __shfl_xor_sync(0xffffffffu, (lane4 & 2) ? a[1] : a[3], 2, 4);
                if (lane4 & 2) { a[0] = e0; a[1] = e1; } else { a[2] = e0; a[3] = e1; }
                float f0 = __shfl_xor_sync(0xffffffffu, (lane4 & 1) ? a[0] : a[1], 1, 4);
                float f1 = __shfl_xor_sync(0xffffffffu, (lane4 & 1) ? a[2] : a[3], 1, 4);
                if (lane4 & 1) { a[0] = f0; a[2] = f1; } else { a[1] = f0; a[3] = f1; }
            }
            cst = fmaf(a[1], cst, a[0] * a[2]);
            float hv = a[3] * tanh_true(cst);
            if (half == 0)
                cc[(pb * ROWS_ + lane4) * 104 + 64 + J] = hv;
        }
        __syncthreads();   // balance: phase1 issued T_ barriers + 1 init; phase2 T_ + 1 + this... 
    }

    // Barrier bookkeeping: phase1 executes 1 (init) + T_ (loop) = 1001 barriers;
    // phase2 executes 1 (init) + T_ (loop) + 1 (tail) = 1002. Rebalance phase1:
    if (p1) __syncthreads();

    // phase2(999): pb=1, wrote h2 into cc[1][r][64..95]
    if (tid < 64) {
        int r = tid & 3, f = tid >> 2;
        const float* hrow = cc + (1 * ROWS_ + r) * 104 + 64;
        float acc = b_fc1[f];
#pragma unroll
        for (int k = 0; k < H2_; ++k) acc = fmaf(hrow[k], w_fc1[f * H2_ + k], acc);
        sfc[r * 16 + f] = fmaxf(acc, 0.0f);
    }
    __syncthreads();
    if (tid < 40) {
        int r = tid & 3, o = tid >> 2;
        float acc = b_fc2[o];
#pragma unroll
        for (int k = 0; k < 16; ++k) acc = fmaf(sfc[r * 16 + k], w_fc2[o * 16 + k], acc);
        out[(row0 + r) * 10 + o] = acc;
    }
}

extern "C" void kernel_launch(void* const* d_in, const int* in_sizes, int n_in,
                              void* d_out, int out_size) {
    const float* x     = (const float*)d_in[0];
    const float* w_ih1 = (const float*)d_in[1];
    const float* w_hh1 = (const float*)d_in[2];
    const float* b_ih1 = (const float*)d_in[3];
    const float* b_hh1 = (const float*)d_in[4];
    const float* w_ih2 = (const float*)d_in[5];
    const float* w_hh2 = (const float*)d_in[6];
    const float* b_ih2 = (const float*)d_in[7];
    const float* b_hh2 = (const float*)d_in[8];
    const float* w_fc1 = (const float*)d_in[9];
    const float* b_fc1 = (const float*)d_in[10];
    const float* w_fc2 = (const float*)d_in[11];
    const float* b_fc2 = (const float*)d_in[12];
    float* out = (float*)d_out;

    dim3 pgrid(NCB_, T_ / PTT_);             // 128 x 10
    xg16_kernel<<<pgrid, 256>>>(x, w_ih1);

    audiolstm_kernel<<<NCB_, THREADS_>>>(
        w_hh1, b_ih1, b_hh1,
        w_ih2, w_hh2, b_ih2, b_hh2,
        w_fc1, b_fc1, w_fc2, b_fc2, out);
}